// round 17
// baseline (speedup 1.0000x reference)
#include <cuda_runtime.h>
#include <math.h>
#include <stdint.h>

// R16: (1) k_sim rebuilt on split-tf32 m16n8k8 MMA (dots on tensor pipe,
// rank on alpha*dot = monotone key, only 2 sigmoids). (2) k_zero folded into
// k_pfin; k_cofin+k_pco fused into k_cp. 6 launches total.

// ---------------- problem constants ----------------
#define T_TOK 4096
#define B_SZ  16
#define CIN   256
#define HEADS 8
#define HDIM  32
#define HD    256
#define SIDE  64
#define M_CT  16
#define BH    128
#define NROWS (T_TOK * B_SZ)   // 65536
#define CSPLIT 4

// ---------------- GEMM tiling (mma.sync m16n8k8 tf32) ----------------
#define KC   32
#define NCH  (CIN / KC)         // 8
#define PADK 36
#define TILE_F (128 * PADK)
#define STAGE_F (2 * TILE_F)
#define DYN_SMEM (2 * STAGE_F * 4)   // 73728 B

// ---------------- scratch ----------------
__device__ float g_q[(size_t)BH * T_TOK * HDIM];
__device__ float g_v[(size_t)BH * T_TOK * HDIM];
__device__ float g_chat[BH * M_CT * HDIM];
__device__ float g_vc[BH * M_CT * HDIM];
__device__ float g_coacc[BH * M_CT * HDIM];
__device__ float g_cnt[BH * M_CT];
__device__ float g_w[(size_t)BH * T_TOK * 2];
__device__ int   g_sel[(size_t)BH * T_TOK];
__device__ float g_pco[(size_t)BH * M_CT * HD];
__device__ float g_ppq[(size_t)BH * M_CT * 32 * 32];
__device__ float g_ppv[(size_t)BH * M_CT * 32 * 32];

// ---------------- helpers ----------------
__device__ __forceinline__ uint32_t smem_u32(const void* p) {
    uint32_t a;
    asm("{ .reg .u64 t; cvta.to.shared.u64 t, %1; cvt.u32.u64 %0, t; }" : "=r"(a) : "l"(p));
    return a;
}
__device__ __forceinline__ void cp16(uint32_t dst, const void* src) {
    asm volatile("cp.async.cg.shared.global [%0], [%1], 16;" :: "r"(dst), "l"(src) : "memory");
}
__device__ __forceinline__ float totf32(float v) {
    uint32_t o;
    asm("cvt.rna.tf32.f32 %0, %1;" : "=r"(o) : "f"(v));
    return __uint_as_float(o);
}
__device__ __forceinline__ void mma_tf32(float* c, const uint32_t* a, const uint32_t* b) {
    asm volatile(
        "mma.sync.aligned.m16n8k8.row.col.f32.tf32.tf32.f32 "
        "{%0,%1,%2,%3},{%4,%5,%6,%7},{%8,%9},{%0,%1,%2,%3};"
        : "+f"(c[0]), "+f"(c[1]), "+f"(c[2]), "+f"(c[3])
        : "r"(a[0]), "r"(a[1]), "r"(a[2]), "r"(a[3]), "r"(b[0]), "r"(b[1]));
}

__device__ __forceinline__ void load_tile(const float* __restrict__ gsrc,
                                          uint32_t sdst, int tid)
{
    const int seg = tid & 7;
    const int r0 = tid >> 3;
#pragma unroll
    for (int i = 0; i < 4; i++) {
        const int r = r0 + i * 32;
        cp16(sdst + (uint32_t)r * (PADK * 4) + seg * 16,
             (const char*)gsrc + (size_t)r * (CIN * 4) + seg * 16);
    }
}

// ---------------- merged GEMM: ct<2 -> q (3-term), ct>=2 -> v (1-term) ----------------
__global__ __launch_bounds__(256, 2)
void k_gemm(const float* __restrict__ x,
            const float* __restrict__ f_w, const float* __restrict__ f_b,
            const float* __restrict__ v_w, const float* __restrict__ v_b)
{
    extern __shared__ float dynf[];
    __shared__ float sbias[128];

    const int tid = threadIdx.x;
    const int wid = tid >> 5;
    const int lane = tid & 31;
    const int group = lane >> 2;
    const int tig = lane & 3;
    const int wm = wid & 1;
    const int wn = wid >> 1;
    const int rowBase = blockIdx.x * 128;
    const int ct = blockIdx.y;
    const bool isQ = (ct < 2);
    const int ctl = isQ ? ct : (ct - 2);

    const float* W = (isQ ? f_w : v_w) + (size_t)(ctl * 128) * CIN;
    const float* bias = (isQ ? f_b : v_b) + ctl * 128;
    if (tid < 128) sbias[tid] = bias[tid];

    const uint32_t sbase = smem_u32(dynf);
    const float* A = x + (size_t)rowBase * CIN;

    float acc[4][4][4];
#pragma unroll
    for (int mi = 0; mi < 4; mi++)
#pragma unroll
        for (int ni = 0; ni < 4; ni++)
#pragma unroll
            for (int r = 0; r < 4; r++) acc[mi][ni][r] = 0.f;

#pragma unroll
    for (int p = 0; p < 2; p++) {
        const uint32_t sb = sbase + p * STAGE_F * 4;
        load_tile(A + p * KC, sb, tid);
        load_tile(W + p * KC, sb + TILE_F * 4, tid);
        asm volatile("cp.async.commit_group;" ::: "memory");
    }

#pragma unroll 1
    for (int c = 0; c < NCH; c++) {
        const int s = c & 1;
        const float* As = dynf + s * STAGE_F;
        const float* Bs = As + TILE_F;
        if (c < NCH - 2) asm volatile("cp.async.wait_group 1;" ::: "memory");
        else             asm volatile("cp.async.wait_group 0;" ::: "memory");
        __syncthreads();
        if (isQ) {
#pragma unroll
            for (int kk8 = 0; kk8 < 4; kk8++) {
                const int kk = kk8 * 8;
                uint32_t ah[4][4], al[4][4], bh[4][2], bl[4][2];
#pragma unroll
                for (int mi = 0; mi < 4; mi++) {
                    const int r0 = wm * 64 + mi * 16 + group;
                    float raw[4];
                    raw[0] = As[r0 * PADK + kk + tig];
                    raw[1] = As[(r0 + 8) * PADK + kk + tig];
                    raw[2] = As[r0 * PADK + kk + tig + 4];
                    raw[3] = As[(r0 + 8) * PADK + kk + tig + 4];
#pragma unroll
                    for (int r = 0; r < 4; r++) {
                        const float h = totf32(raw[r]);
                        ah[mi][r] = __float_as_uint(h);
                        al[mi][r] = __float_as_uint(totf32(raw[r] - h));
                    }
                }
#pragma unroll
                for (int ni = 0; ni < 4; ni++) {
                    const int cb = wn * 32 + ni * 8 + group;
                    float raw[2];
                    raw[0] = Bs[cb * PADK + kk + tig];
                    raw[1] = Bs[cb * PADK + kk + tig + 4];
#pragma unroll
                    for (int r = 0; r < 2; r++) {
                        const float h = totf32(raw[r]);
                        bh[ni][r] = __float_as_uint(h);
                        bl[ni][r] = __float_as_uint(totf32(raw[r] - h));
                    }
                }
#pragma unroll
                for (int mi = 0; mi < 4; mi++)
#pragma unroll
                    for (int ni = 0; ni < 4; ni++) {
                        mma_tf32(acc[mi][ni], al[mi], bh[ni]);
                        mma_tf32(acc[mi][ni], ah[mi], bl[ni]);
                        mma_tf32(acc[mi][ni], ah[mi], bh[ni]);
                    }
            }
        } else {
#pragma unroll
            for (int kk8 = 0; kk8 < 4; kk8++) {
                const int kk = kk8 * 8;
                uint32_t a[4][4], b[4][2];
#pragma unroll
                for (int mi = 0; mi < 4; mi++) {
                    const int r0 = wm * 64 + mi * 16 + group;
                    a[mi][0] = __float_as_uint(totf32(As[r0 * PADK + kk + tig]));
                    a[mi][1] = __float_as_uint(totf32(As[(r0 + 8) * PADK + kk + tig]));
                    a[mi][2] = __float_as_uint(totf32(As[r0 * PADK + kk + tig + 4]));
                    a[mi][3] = __float_as_uint(totf32(As[(r0 + 8) * PADK + kk + tig + 4]));
                }
#pragma unroll
                for (int ni = 0; ni < 4; ni++) {
                    const int cb = wn * 32 + ni * 8 + group;
                    b[ni][0] = __float_as_uint(totf32(Bs[cb * PADK + kk + tig]));
                    b[ni][1] = __float_as_uint(totf32(Bs[cb * PADK + kk + tig + 4]));
                }
#pragma unroll
                for (int mi = 0; mi < 4; mi++)
#pragma unroll
                    for (int ni = 0; ni < 4; ni++)
                        mma_tf32(acc[mi][ni], a[mi], b[ni]);
            }
        }
        __syncthreads();
        if (c + 2 < NCH) {
            const uint32_t sb = sbase + s * STAGE_F * 4;
            load_tile(A + (c + 2) * KC, sb, tid);
            load_tile(W + (c + 2) * KC, sb + TILE_F * 4, tid);
            asm volatile("cp.async.commit_group;" ::: "memory");
        }
    }

    // ---- epilogue part 1: biased stores ----
    float* const base = isQ ? g_q : g_v;
#pragma unroll
    for (int mi = 0; mi < 4; mi++)
#pragma unroll
        for (int ni = 0; ni < 4; ni++) {
            const int row_l = wm * 64 + mi * 16 + group;
            const int col_l = wn * 32 + ni * 8 + 2 * tig;
            const float bx = sbias[col_l], by = sbias[col_l + 1];
#pragma unroll
            for (int h2 = 0; h2 < 2; h2++) {
                const int n_g = rowBase + row_l + h2 * 8;
                float2 val;
                val.x = acc[mi][ni][h2 * 2 + 0] + bx;
                val.y = acc[mi][ni][h2 * 2 + 1] + by;
                const int t = n_g >> 4, bb = n_g & 15;
                const int cLoc = ctl * 128 + col_l;
                const int h = cLoc >> 5, d = cLoc & 31;
                *(float2*)(base + (((size_t)bb * HEADS + h) * T_TOK + t) * HDIM + d) = val;
            }
        }

    // ---- epilogue part 2: pool partials ----
    float* const spool = dynf;
#pragma unroll
    for (int ni = 0; ni < 4; ni++)
#pragma unroll
        for (int h2 = 0; h2 < 2; h2++)
#pragma unroll
            for (int cc = 0; cc < 2; cc++) {
                float p = acc[0][ni][h2 * 2 + cc] + acc[1][ni][h2 * 2 + cc]
                        + acc[2][ni][h2 * 2 + cc] + acc[3][ni][h2 * 2 + cc];
                const int b = group + 8 * h2;
                const int d = ni * 8 + 2 * tig + cc;
                spool[((wm * 4 + wn) * 16 + b) * 37 + d] = p;
            }
    __syncthreads();

    const int bx_ = blockIdx.x;
    const int m = ((bx_ >> 7) << 2) | ((bx_ >> 1) & 3);
    const int slot = (((bx_ >> 3) & 15) << 1) | (bx_ & 1);
    float* const pp = isQ ? g_ppq : g_ppv;
    for (int i = tid; i < 2048; i += 256) {
        const int wni = i >> 9, bi = (i >> 5) & 15, di = i & 31;
        const float s = spool[((0 * 4 + wni) * 16 + bi) * 37 + di]
                      + spool[((1 * 4 + wni) * 16 + bi) * 37 + di];
        const int hg = ctl * 4 + wni;
        const int bh = bi * HEADS + hg;
        pp[(((size_t)bh * M_CT + m) * 32 + slot) * 32 + di] = s;
    }
}

// ---------------- pool finalize (+ zero the center accumulators) ----------------
__global__ __launch_bounds__(256)
void k_pfin(const float* __restrict__ f_b, const float* __restrict__ v_b)
{
    const int wid = threadIdx.x >> 5, lane = threadIdx.x & 31;
    const int cell = blockIdx.x * 8 + wid;
    const int bh = cell >> 4;
    const int h = bh & 7;

    const float* pq = g_ppq + (size_t)cell * 1024 + lane;
    const float* pv = g_ppv + (size_t)cell * 1024 + lane;
    float sq = 0.f, sv = 0.f;
#pragma unroll
    for (int s = 0; s < 32; s++) { sq += pq[s * 32]; sv += pv[s * 32]; }

    const float aq = sq * (1.f / 256.f) + f_b[h * 32 + lane];
    const float av = sv * (1.f / 256.f) + v_b[h * 32 + lane];
    float nn = aq * aq;
#pragma unroll
    for (int o = 16; o; o >>= 1) nn += __shfl_xor_sync(0xffffffffu, nn, o);
    const float denom = fmaxf(sqrtf(nn), 1e-12f);
    g_chat[cell * 32 + lane] = aq / denom;
    g_vc[cell * 32 + lane] = av;

    // fused zeroing (grid covers exactly BH*M_CT*HDIM elements)
    const int gid = blockIdx.x * 256 + threadIdx.x;
    g_coacc[gid] = 0.f;
    if (gid < BH * M_CT) g_cnt[gid] = 0.f;
}

// ---------------- similarity + top-2 via split-tf32 MMA ----------------
// grid (BH, T/128), 128 threads (4 warps); warp handles 32 tokens.
__global__ __launch_bounds__(128)
void k_sim2(const float* __restrict__ alpha, const float* __restrict__ beta)
{
    __shared__ float ch_hi[16][33];
    __shared__ float ch_lo[16][33];
    __shared__ float qs[128][36];
    __shared__ float sdots[4][32][17];
    __shared__ float rn[128];

    const int bh = blockIdx.x;
    const int t0 = blockIdx.y * 128;
    const int tid = threadIdx.x;
    const int w = tid >> 5;
    const int lane = tid & 31;
    const int group = lane >> 2;
    const int tig = lane & 3;

    for (int i = tid; i < 512; i += 128) {
        const float v = g_chat[bh * 512 + i];
        const float h = totf32(v);
        ch_hi[i >> 5][i & 31] = h;
        ch_lo[i >> 5][i & 31] = totf32(v - h);
    }
    {
        const float4* src = (const float4*)(g_q + ((size_t)bh * T_TOK + t0 + tid) * HDIM);
        float qn = 0.f;
#pragma unroll
        for (int c = 0; c < 8; c++) {
            float4 v = src[c];
            qn += v.x * v.x + v.y * v.y + v.z * v.z + v.w * v.w;
            qs[tid][c * 4 + 0] = v.x; qs[tid][c * 4 + 1] = v.y;
            qs[tid][c * 4 + 2] = v.z; qs[tid][c * 4 + 3] = v.w;
        }
        rn[tid] = qn;
    }
    __syncthreads();

    float acc[2][2][4];
#pragma unroll
    for (int mi = 0; mi < 2; mi++)
#pragma unroll
        for (int ni = 0; ni < 2; ni++)
#pragma unroll
            for (int r = 0; r < 4; r++) acc[mi][ni][r] = 0.f;

#pragma unroll
    for (int kk8 = 0; kk8 < 4; kk8++) {
        const int kk = kk8 * 8;
        uint32_t ah[2][4], al[2][4], bhv[2][2], blv[2][2];
#pragma unroll
        for (int mi = 0; mi < 2; mi++) {
            const int r0 = w * 32 + mi * 16 + group;
            float raw[4];
            raw[0] = qs[r0][kk + tig];
            raw[1] = qs[r0 + 8][kk + tig];
            raw[2] = qs[r0][kk + tig + 4];
            raw[3] = qs[r0 + 8][kk + tig + 4];
#pragma unroll
            for (int r = 0; r < 4; r++) {
                const float h = totf32(raw[r]);
                ah[mi][r] = __float_as_uint(h);
                al[mi][r] = __float_as_uint(totf32(raw[r] - h));
            }
        }
#pragma unroll
        for (int ni = 0; ni < 2; ni++) {
            const int cb = ni * 8 + group;
            bhv[ni][0] = __float_as_uint(ch_hi[cb][kk + tig]);
            bhv[ni][1] = __float_as_uint(ch_hi[cb][kk + tig + 4]);
            blv[ni][0] = __float_as_uint(ch_lo[cb][kk + tig]);
            blv[ni][1] = __float_as_uint(ch_lo[cb][kk + tig + 4]);
        }
#pragma unroll
        for (int mi = 0; mi < 2; mi++)
#pragma unroll
            for (int ni = 0; ni < 2; ni++) {
                mma_tf32(acc[mi][ni], al[mi], bhv[ni]);
                mma_tf32(acc[mi][ni], ah[mi], blv[ni]);
                mma_tf32(acc[mi][ni], ah[mi], bhv[ni]);
            }
    }

#pragma unroll
    for (int mi = 0; mi < 2; mi++)
#pragma unroll
        for (int ni = 0; ni < 2; ni++)
#pragma unroll
            for (int h2 = 0; h2 < 2; h2++) {
                const int row = mi * 16 + group + h2 * 8;
                const int col = ni * 8 + 2 * tig;
                sdots[w][row][col] = acc[mi][ni][h2 * 2 + 0];
                sdots[w][row][col + 1] = acc[mi][ni][h2 * 2 + 1];
            }
    __syncwarp();

    const float a = alpha[0], b = beta[0];
    const float rq = 1.f / fmaxf(sqrtf(rn[tid]), 1e-12f);
    float key[16];
#pragma unroll
    for (int m = 0; m < 16; m++) key[m] = a * sdots[w][lane][m];

    int i0 = 0; float v0 = key[0];
#pragma unroll
    for (int m = 1; m < 16; m++) if (key[m] > v0) { v0 = key[m]; i0 = m; }
    int i1 = -1; float v1 = -3.4e38f;
#pragma unroll
    for (int m = 0; m < 16; m++) if (m != i0 && key[m] > v1) { v1 = key[m]; i1 = m; }

    const float z0 = b + v0 * rq;
    const float z1 = b + v1 * rq;
    const float s0 = 1.f / (1.f + expf(-z0));
    const float s1 = 1.f / (1.f + expf(-z1));
    const float p0 = s0 * s0, p1 = s1 * s1;
    const float inv = 1.f / (p0 + p1 + 1e-6f);
    const size_t o = (size_t)bh * T_TOK + t0 + tid;
    g_w[o * 2 + 0] = p0 * inv;
    g_w[o * 2 + 1] = p1 * inv;
    g_sel[o] = i0 | (i1 << 8);
}

// ---------------- centers_out partial sums ----------------
__global__ __launch_bounds__(256)
void k_centers()
{
    const int bh = blockIdx.x;
    const int tBase = blockIdx.y * (T_TOK / CSPLIT);
    const int wi = threadIdx.x >> 5, lane = threadIdx.x & 31;

    float acc[16], wacc[16];
#pragma unroll
    for (int m = 0; m < 16; m++) { acc[m] = 0.f; wacc[m] = 0.f; }

#pragma unroll 2
    for (int t = tBase + wi; t < tBase + T_TOK / CSPLIT; t += 8) {
        const size_t o = (size_t)bh * T_TOK + t;
        const float vv = g_v[o * HDIM + lane];
        const float2 w01 = *(const float2*)(g_w + o * 2);
        const int sel = g_sel[o];
        const int i0 = sel & 255, i1 = sel >> 8;
#pragma unroll
        for (int m = 0; m < 16; m++) {
            const float w = (m == i0) ? w01.x : ((m == i1) ? w01.y : 0.f);
            acc[m] = fmaf(w, vv, acc[m]);
            wacc[m] += w;
        }
    }

    __shared__ float sacc[8][16][32];
    __shared__ float swacc[8][16];
#pragma unroll
    for (int m = 0; m < 16; m++) sacc[wi][m][lane] = acc[m];
    if (lane == 0) {
#pragma unroll
        for (int m = 0; m < 16; m++) swacc[wi][m] = wacc[m];
    }
    __syncthreads();

    for (int i = threadIdx.x; i < 512; i += 256) {
        const int m = i >> 5, d = i & 31;
        float s = 0.f;
#pragma unroll
        for (int w = 0; w < 8; w++) s += sacc[w][m][d];
        atomicAdd(&g_coacc[bh * 512 + i], s);
    }
    if (threadIdx.x < 16) {
        float s = 0.f;
#pragma unroll
        for (int w = 0; w < 8; w++) s += swacc[w][threadIdx.x];
        atomicAdd(&g_cnt[bh * 16 + threadIdx.x], s);
    }
}

// ---------------- fused centers_out finalize + projection ----------------
__global__ __launch_bounds__(256)
void k_cp(const float* __restrict__ proj_w)
{
    const int bh = blockIdx.x;
    const int h = bh & 7;
    const int cout = threadIdx.x;
    __shared__ float sco[512];
    for (int i = cout; i < 512; i += 256) {
        const int m = i >> 5;
        sco[i] = (g_coacc[bh * 512 + i] + g_vc[bh * 512 + i]) / (g_cnt[bh * 16 + m] + 1.f);
    }
    __syncthreads();

    float wrow[32];
    const float4* wp = (const float4*)(proj_w + (size_t)cout * 256 + h * 32);
#pragma unroll
    for (int i = 0; i < 8; i++) {
        float4 v = wp[i];
        wrow[i * 4 + 0] = v.x; wrow[i * 4 + 1] = v.y;
        wrow[i * 4 + 2] = v.z; wrow[i * 4 + 3] = v.w;
    }
#pragma unroll
    for (int m = 0; m < 16; m++) {
        float s = 0.f;
#pragma unroll
        for (int d = 0; d < 32; d++) s = fmaf(wrow[d], sco[m * 32 + d], s);
        g_pco[((size_t)bh * 16 + m) * HD + cout] = s;
    }
}

// ---------------- final mix ----------------
__global__ __launch_bounds__(256)
void k_mix(const float* __restrict__ proj_b, float* __restrict__ out)
{
    const int b = blockIdx.x;
    const int tBase = blockIdx.y * 64;
    const int tid = threadIdx.x;

    __shared__ float spco[16 * 256];
    __shared__ float sw[64 * 2];
    __shared__ int ssel[64];

    float acc[64];
#pragma unroll
    for (int t = 0; t < 64; t++) acc[t] = 0.f;

#pragma unroll 1
    for (int h = 0; h < 8; h++) {
        const int bh = b * 8 + h;
        __syncthreads();
        const float* src = g_pco + (size_t)bh * 16 * HD;
#pragma unroll
        for (int i = 0; i < 16; i++) spco[i * 256 + tid] = src[i * 256 + tid];
        if (tid < 64) {
            const size_t o = (size_t)bh * T_TOK + tBase + tid;
            ((float2*)sw)[tid] = *(const float2*)(g_w + o * 2);
            ssel[tid] = g_sel[o];
        }
        __syncthreads();
#pragma unroll
        for (int t = 0; t < 64; t++) {
            const float w0 = sw[2 * t], w1 = sw[2 * t + 1];
            const int sel = ssel[t];
            const float p0 = spco[(sel & 255) * 256 + tid];
            const float p1 = spco[(sel >> 8) * 256 + tid];
            acc[t] = fmaf(w0, p0, fmaf(w1, p1, acc[t]));
        }
    }
    const float bias = proj_b[tid];
#pragma unroll
    for (int t = 0; t < 64; t++)
        out[((size_t)(tBase + t) * B_SZ + b) * HD + tid] = acc[t] + bias;
}

// ---------------- launch ----------------
extern "C" void kernel_launch(void* const* d_in, const int* in_sizes, int n_in,
                              void* d_out, int out_size)
{
    const float* x      = (const float*)d_in[0];
    const float* f_w    = (const float*)d_in[1];
    const float* f_b    = (const float*)d_in[2];
    const float* v_w    = (const float*)d_in[3];
    const float* v_b    = (const float*)d_in[4];
    const float* proj_w = (const float*)d_in[5];
    const float* proj_b = (const float*)d_in[6];
    const float* alpha  = (const float*)d_in[7];
    const float* beta   = (const float*)d_in[8];
    float* out = (float*)d_out;

    cudaFuncSetAttribute(k_gemm, cudaFuncAttributeMaxDynamicSharedMemorySize, DYN_SMEM);

    k_gemm<<<dim3(NROWS / 128, 4), 256, DYN_SMEM>>>(x, f_w, f_b, v_w, v_b);
    k_pfin<<<BH * M_CT / 8, 256>>>(f_b, v_b);
    k_sim2<<<dim3(BH, T_TOK / 128), 128>>>(alpha, beta);
    k_centers<<<dim3(BH, CSPLIT), 256>>>();
    k_cp<<<BH, 256>>>(proj_w);
    k_mix<<<dim3(B_SZ, T_TOK / 64), 256>>>(proj_b, out);
}